// round 17
// baseline (speedup 1.0000x reference)
#include <cuda_runtime.h>
#include <cuda_fp16.h>
#include <cstdint>

#define THREADS 256
#define M_TILE  128

// ---------------- SMEM layout (bytes), MMA buffers 1024-aligned ----------------
#define OFF_B1   0
#define OFF_B2   256
#define OFF_X    1024                  // 128 x 64 fp16 (128B rows, SW128) = 16384
#define OFF_W1   (OFF_X + 16384)       // 17408  (192 x 64 fp16) = 24576
#define OFF_W2   (OFF_W1 + 24576)      // 41984  (64 x 64 fp16)  = 8192
#define SMEM_BYTES (OFF_W2 + 8192)     // 50176 -> 4 CTAs/SM (if regs <= 64)

// ---------------- helpers ----------------
__device__ __forceinline__ uint32_t smem_u32(const void* p) {
    uint32_t a;
    asm("{ .reg .u64 t; cvta.to.shared.u64 t, %1; cvt.u32.u64 %0, t; }" : "=r"(a) : "l"(p));
    return a;
}
__device__ __forceinline__ uint32_t sw128(uint32_t o) { return o ^ ((o >> 3) & 0x70); }

__device__ __forceinline__ uint32_t f2h2(float a, float b) {
    __half2 h = __floats2half2_rn(a, b);
    return *(uint32_t*)&h;
}

__device__ __forceinline__ void ldsm4(uint32_t r[4], uint32_t addr) {
    asm volatile("ldmatrix.sync.aligned.m8n8.x4.shared.b16 {%0,%1,%2,%3}, [%4];"
        : "=r"(r[0]), "=r"(r[1]), "=r"(r[2]), "=r"(r[3]) : "r"(addr));
}
__device__ __forceinline__ void ldsm4t(uint32_t r[4], uint32_t addr) {
    asm volatile("ldmatrix.sync.aligned.m8n8.x4.trans.shared.b16 {%0,%1,%2,%3}, [%4];"
        : "=r"(r[0]), "=r"(r[1]), "=r"(r[2]), "=r"(r[3]) : "r"(addr));
}
__device__ __forceinline__ void mma16816(float c[4], const uint32_t a[4], const uint32_t b[2]) {
    asm volatile(
        "mma.sync.aligned.m16n8k16.row.col.f32.f16.f16.f32 "
        "{%0,%1,%2,%3}, {%4,%5,%6,%7}, {%8,%9}, {%0,%1,%2,%3};"
        : "+f"(c[0]), "+f"(c[1]), "+f"(c[2]), "+f"(c[3])
        : "r"(a[0]), "r"(a[1]), "r"(a[2]), "r"(a[3]), "r"(b[0]), "r"(b[1]));
}
__device__ __forceinline__ uint32_t frag_addr(uint32_t base, int rbase, int cbase, int lane) {
    int row  = rbase + (lane & 15);
    int colb = cbase * 2 + (lane & 16);
    return base + sw128((uint32_t)(row * 128 + colb));
}
__device__ __forceinline__ void prefetch_l2(const void* p) {
    asm volatile("prefetch.global.L2 [%0];" :: "l"(p));
}

__global__ __launch_bounds__(THREADS, 4)
void edge_mlp_f16(const float* __restrict__ src, const float* __restrict__ dst,
                  const float* __restrict__ ea,
                  const float* __restrict__ W1, const float* __restrict__ b1,
                  const float* __restrict__ W2, const float* __restrict__ b2,
                  float* __restrict__ out, int E, int ntiles)
{
    extern __shared__ char smem[];
    const uint32_t sb = smem_u32(smem);
    const int tid = threadIdx.x;
    const int lid = tid & 31;
    const int wid = tid >> 5;

    const int wm = wid & 3;   // M group: rows 32*wm .. +31
    const int wn = wid >> 2;  // N group: cols 32*wn .. +31

    // ================= ONE-TIME: biases + fp16 weights =================
    if (tid < 64) {
        ((float*)(smem + OFF_B1))[tid] = b1[tid];
        ((float*)(smem + OFF_B2))[tid] = b2[tid];
    }
    #pragma unroll
    for (int i = 0; i < 12; ++i) {
        int idx = tid + i * THREADS;               // float4 index, 0..3071
        float4 v = ((const float4*)W1)[idx];
        uint32_t off = sw128((uint32_t)((idx >> 4) * 128 + (idx & 15) * 8));
        *(uint2*)(smem + OFF_W1 + off) = make_uint2(f2h2(v.x, v.y), f2h2(v.z, v.w));
    }
    #pragma unroll
    for (int i = 0; i < 4; ++i) {
        int idx = tid + i * THREADS;               // 0..1023
        float4 v = ((const float4*)W2)[idx];
        uint32_t off = sw128((uint32_t)((idx >> 4) * 128 + (idx & 15) * 8));
        *(uint2*)(smem + OFF_W2 + off) = make_uint2(f2h2(v.x, v.y), f2h2(v.z, v.w));
    }

    float acc[2][4][4];
    #pragma unroll
    for (int mt = 0; mt < 2; ++mt)
        #pragma unroll
        for (int nt = 0; nt < 4; ++nt)
            #pragma unroll
            for (int j = 0; j < 4; ++j) acc[mt][nt][j] = 0.f;

    // ---- X staging: 4 batches of 2 LDGs (8 live staging regs) ----
    auto stage_x = [&](const float* __restrict__ p, int e0, const float* __restrict__ pre) {
        if (pre) prefetch_l2((const char*)pre + (size_t)tid * 128);
        #pragma unroll
        for (int g = 0; g < 4; ++g) {
            float4 v[2];
            #pragma unroll
            for (int i = 0; i < 2; ++i) {
                int idx = tid + (g * 2 + i) * THREADS;   // 0..2047
                int e = e0 + (idx >> 4);
                v[i] = (e < E) ? ((const float4*)p)[(size_t)e * 16 + (idx & 15)]
                               : make_float4(0.f, 0.f, 0.f, 0.f);
            }
            #pragma unroll
            for (int i = 0; i < 2; ++i) {
                int idx = tid + (g * 2 + i) * THREADS;
                uint32_t off = sw128((uint32_t)((idx >> 4) * 128 + (idx & 15) * 8));
                *(uint2*)(smem + OFF_X + off) =
                    make_uint2(f2h2(v[i].x, v[i].y), f2h2(v[i].z, v[i].w));
            }
        }
    };

    // one 16-wide k-step, 1 term: acc += x*w
    auto kstep = [&](int kk, uint32_t wb, int kg) {
        uint32_t bf[2][4], af[2][4];
        ldsm4t(bf[0], frag_addr(wb, kg, wn * 32,      lid));
        ldsm4t(bf[1], frag_addr(wb, kg, wn * 32 + 16, lid));
        ldsm4(af[0], frag_addr(sb + OFF_X, wm * 32,      kk, lid));
        ldsm4(af[1], frag_addr(sb + OFF_X, wm * 32 + 16, kk, lid));
        #pragma unroll
        for (int mt = 0; mt < 2; ++mt)
            #pragma unroll
            for (int nt = 0; nt < 4; ++nt)
                mma16816(acc[mt][nt], af[mt], &bf[nt >> 1][(nt & 1) * 2]);
    };

    // ================= persistent tile loop =================
    for (int t = blockIdx.x; t < ntiles; t += gridDim.x) {
        const int e0 = t * M_TILE;

        stage_x(src, e0, dst + (size_t)e0 * 64);
        __syncthreads();
        #pragma unroll
        for (int ks = 0; ks < 4; ++ks) kstep(ks * 16, sb + OFF_W1, ks * 16);
        __syncthreads();

        stage_x(dst, e0, ea + (size_t)e0 * 64);
        __syncthreads();
        #pragma unroll
        for (int ks = 0; ks < 4; ++ks) kstep(ks * 16, sb + OFF_W1, 64 + ks * 16);
        __syncthreads();

        {
            int tn = t + gridDim.x;
            const float* nxt = (tn < ntiles) ? src + (size_t)tn * M_TILE * 64
                                             : src + (size_t)e0 * 64;
            stage_x(ea, e0, nxt);
        }
        __syncthreads();
        #pragma unroll
        for (int ks = 0; ks < 4; ++ks) kstep(ks * 16, sb + OFF_W1, 128 + ks * 16);
        __syncthreads();                           // GEMM1 reads done; X free for H

        // ---- bias1 + ReLU -> single fp16 H plane (reuse X) ----
        {
            const float* b1s = (const float*)(smem + OFF_B1);
            #pragma unroll
            for (int mt = 0; mt < 2; ++mt)
                #pragma unroll
                for (int nt = 0; nt < 4; ++nt) {
                    int row = wm * 32 + mt * 16 + (lid >> 2);
                    int col = wn * 32 + nt * 8 + (lid & 3) * 2;
                    float bc0 = b1s[col], bc1 = b1s[col + 1];
                    float h0 = fmaxf(acc[mt][nt][0] + bc0, 0.f);
                    float h1 = fmaxf(acc[mt][nt][1] + bc1, 0.f);
                    float h2 = fmaxf(acc[mt][nt][2] + bc0, 0.f);
                    float h3 = fmaxf(acc[mt][nt][3] + bc1, 0.f);
                    uint32_t oA = sw128((uint32_t)(row * 128 + col * 2));
                    uint32_t oB = sw128((uint32_t)((row + 8) * 128 + col * 2));
                    *(uint32_t*)(smem + OFF_X + oA) = f2h2(h0, h1);
                    *(uint32_t*)(smem + OFF_X + oB) = f2h2(h2, h3);
                    acc[mt][nt][0] = acc[mt][nt][1] = acc[mt][nt][2] = acc[mt][nt][3] = 0.f;
                }
        }
        __syncthreads();

        // ================= GEMM2 (K = 64) =================
        #pragma unroll
        for (int ks = 0; ks < 4; ++ks) kstep(ks * 16, sb + OFF_W2, ks * 16);

        // ---- epilogue: + bias2, float2 stores; reset acc for next tile ----
        {
            const float* b2s = (const float*)(smem + OFF_B2);
            #pragma unroll
            for (int mt = 0; mt < 2; ++mt)
                #pragma unroll
                for (int nt = 0; nt < 4; ++nt) {
                    int row = wm * 32 + mt * 16 + (lid >> 2);
                    int col = wn * 32 + nt * 8 + (lid & 3) * 2;
                    float bc0 = b2s[col], bc1 = b2s[col + 1];
                    int eA = e0 + row, eB = e0 + row + 8;
                    if (eA < E)
                        *(float2*)&out[(size_t)eA * 64 + col] =
                            make_float2(acc[mt][nt][0] + bc0, acc[mt][nt][1] + bc1);
                    if (eB < E)
                        *(float2*)&out[(size_t)eB * 64 + col] =
                            make_float2(acc[mt][nt][2] + bc0, acc[mt][nt][3] + bc1);
                    acc[mt][nt][0] = acc[mt][nt][1] = acc[mt][nt][2] = acc[mt][nt][3] = 0.f;
                }
        }
        __syncthreads();                           // H reads done before next stage_x
    }
}

extern "C" void kernel_launch(void* const* d_in, const int* in_sizes, int n_in,
                              void* d_out, int out_size)
{
    const float* src = (const float*)d_in[0];
    const float* dst = (const float*)d_in[1];
    const float* ea  = (const float*)d_in[2];
    const float* W1  = (const float*)d_in[5];
    const float* b1  = (const float*)d_in[6];
    const float* W2  = (const float*)d_in[7];
    const float* b2  = (const float*)d_in[8];
    float* out = (float*)d_out;

    int E = in_sizes[0] / 64;
    int ntiles = (E + M_TILE - 1) / M_TILE;

    cudaFuncSetAttribute(edge_mlp_f16,
                         cudaFuncAttributeMaxDynamicSharedMemorySize, SMEM_BYTES);

    int grid = 4 * 148;
    if (grid > ntiles) grid = ntiles;
    edge_mlp_f16<<<grid, THREADS, SMEM_BYTES>>>(src, dst, ea, W1, b1, W2, b2, out, E, ntiles);
}